// round 1
// baseline (speedup 1.0000x reference)
#include <cuda_runtime.h>
#include <cstdint>

// Problem constants: student/teacher [B=2, V=2, C=64, HW=1024], labels [2,2,1024]
#define N_TOT  4096   // B*V*HW
#define C_DIM  64
#define HW_DIM 1024
#define NIMG   2048   // V*HW  (rows per image; only same-image pairs matter)
#define RTILE  16     // anchor rows per block

// Scratch (device globals: no allocation allowed)
__device__ float g_sfT[C_DIM * N_TOT];   // normalized student, [C][N]
__device__ float g_tfT[C_DIM * N_TOT];   // normalized teacher, [C][N]
__device__ float g_mlpp[N_TOT];
__device__ float g_cnt[N_TOT];

// ---------- packed f32x2 helpers (Blackwell FFMA2 via PTX) ----------
__device__ __forceinline__ unsigned long long pack2(float lo, float hi) {
    unsigned long long r;
    asm("mov.b64 %0, {%1, %2};" : "=l"(r) : "f"(lo), "f"(hi));
    return r;
}
__device__ __forceinline__ void unpack2(unsigned long long v, float& lo, float& hi) {
    asm("mov.b64 {%0, %1}, %2;" : "=f"(lo), "=f"(hi) : "l"(v));
}
__device__ __forceinline__ unsigned long long ffma2(unsigned long long a,
                                                    unsigned long long b,
                                                    unsigned long long c) {
    unsigned long long d;
    asm("fma.rn.f32x2 %0, %1, %2, %3;" : "=l"(d) : "l"(a), "l"(b), "l"(c));
    return d;
}

// ---------- kernel 1: L2-normalize and transpose to [C][N] ----------
__global__ __launch_bounds__(256) void scl_normalize_kernel(
    const float* __restrict__ stu, const float* __restrict__ tea) {
    int n  = blockIdx.x * blockDim.x + threadIdx.x;   // 0..N_TOT-1
    int bv = n >> 10;                                  // HW_DIM = 1024
    int p  = n & (HW_DIM - 1);

    const float* sb = stu + (size_t)bv * C_DIM * HW_DIM + p;
    float v[C_DIM];
    float ss = 0.f;
#pragma unroll
    for (int c = 0; c < C_DIM; c++) { v[c] = sb[c * HW_DIM]; ss += v[c] * v[c]; }
    float inv = 1.f / fmaxf(sqrtf(ss), 1e-12f);
#pragma unroll
    for (int c = 0; c < C_DIM; c++) g_sfT[c * N_TOT + n] = v[c] * inv;

    const float* tb = tea + (size_t)bv * C_DIM * HW_DIM + p;
    ss = 0.f;
#pragma unroll
    for (int c = 0; c < C_DIM; c++) { v[c] = tb[c * HW_DIM]; ss += v[c] * v[c]; }
    inv = 1.f / fmaxf(sqrtf(ss), 1e-12f);
#pragma unroll
    for (int c = 0; c < C_DIM; c++) g_tfT[c * N_TOT + n] = v[c] * inv;
}

// per-pair softmax bookkeeping (shift M=10 since |logit| <= 1/T = 10)
__device__ __forceinline__ void scl_acc(float dot, int j, int irow_g,
                                        int labj, int labi,
                                        float& Zr, float& Sr, float& Cr) {
    float l = dot * 10.f;                // 1/TEMPERATURE
    float e = __expf(l - 10.f);
    if (j != irow_g) {                   // self-similarity excluded
        Zr += e;                         // denominator: all same-image except self
        if (labj == labi) {              // numerator: same class, except self
            Sr += l;
            Cr += 1.f;
        }
    }
}

// ---------- kernel 2: fused masked contrastive log-softmax ----------
// One block = RTILE anchor rows, streaming over this image's 2048 columns.
__global__ __launch_bounds__(256) void scl_main_kernel(const int* __restrict__ labels) {
    __shared__ __align__(8) float sf_s[C_DIM][RTILE];   // [c][r], row-pairs LDS.64-able
    __shared__ int   lab_s[RTILE];
    __shared__ float redZ[8][RTILE], redS[8][RTILE], redC[8][RTILE];

    int tid = threadIdx.x;                    // 256 threads
    int i0  = blockIdx.x * RTILE;

    for (int idx = tid; idx < C_DIM * RTILE; idx += 256) {
        int c = idx >> 4, r = idx & (RTILE - 1);
        sf_s[c][r] = g_sfT[c * N_TOT + i0 + r];
    }
    if (tid < RTILE) lab_s[tid] = labels[i0 + tid];
    __syncthreads();

    int jbase = i0 & ~(NIMG - 1);             // this image's column block

    float Z[RTILE], S[RTILE], CT[RTILE];
#pragma unroll
    for (int r = 0; r < RTILE; r++) { Z[r] = 0.f; S[r] = 0.f; CT[r] = 0.f; }

    // 4 groups x (2 columns per thread x 256 threads) = 2048 columns
    for (int g = 0; g < 4; g++) {
        int j0 = jbase + g * 512 + tid;
        int j1 = j0 + 256;

        unsigned long long acc0[RTILE / 2], acc1[RTILE / 2];  // f32x2: rows (2rp, 2rp+1)
#pragma unroll
        for (int rp = 0; rp < RTILE / 2; rp++) { acc0[rp] = 0ull; acc1[rp] = 0ull; }

#pragma unroll
        for (int c = 0; c < C_DIM; c++) {
            float t0 = g_tfT[c * N_TOT + j0];
            float t1 = g_tfT[c * N_TOT + j1];
            unsigned long long tp0 = pack2(t0, t0);
            unsigned long long tp1 = pack2(t1, t1);
#pragma unroll
            for (int rp = 0; rp < RTILE / 2; rp++) {
                unsigned long long sfp =
                    *(const unsigned long long*)&sf_s[c][rp * 2];  // LDS.64 broadcast
                acc0[rp] = ffma2(tp0, sfp, acc0[rp]);
                acc1[rp] = ffma2(tp1, sfp, acc1[rp]);
            }
        }

        int lj0 = labels[j0];
        int lj1 = labels[j1];
#pragma unroll
        for (int rp = 0; rp < RTILE / 2; rp++) {
            int r0 = rp * 2, r1 = rp * 2 + 1;
            float d00, d01, d10, d11;
            unpack2(acc0[rp], d00, d01);
            unpack2(acc1[rp], d10, d11);
            scl_acc(d00, j0, i0 + r0, lj0, lab_s[r0], Z[r0], S[r0], CT[r0]);
            scl_acc(d01, j0, i0 + r1, lj0, lab_s[r1], Z[r1], S[r1], CT[r1]);
            scl_acc(d10, j1, i0 + r0, lj1, lab_s[r0], Z[r0], S[r0], CT[r0]);
            scl_acc(d11, j1, i0 + r1, lj1, lab_s[r1], Z[r1], S[r1], CT[r1]);
        }
    }

    // deterministic block reduction: warp shuffles, then cross-warp in smem
#pragma unroll
    for (int r = 0; r < RTILE; r++) {
#pragma unroll
        for (int off = 16; off > 0; off >>= 1) {
            Z[r]  += __shfl_down_sync(0xffffffffu, Z[r],  off);
            S[r]  += __shfl_down_sync(0xffffffffu, S[r],  off);
            CT[r] += __shfl_down_sync(0xffffffffu, CT[r], off);
        }
    }
    int warp = tid >> 5, lane = tid & 31;
    if (lane == 0) {
#pragma unroll
        for (int r = 0; r < RTILE; r++) {
            redZ[warp][r] = Z[r]; redS[warp][r] = S[r]; redC[warp][r] = CT[r];
        }
    }
    __syncthreads();
    if (tid < RTILE) {
        float z = 0.f, s = 0.f, ct = 0.f;
#pragma unroll
        for (int w = 0; w < 8; w++) { z += redZ[w][tid]; s += redS[w][tid]; ct += redC[w][tid]; }
        // mean log prob of positives with fixed shift M=10
        float mlpp = (s - ct * (10.f + logf(z))) / (ct + 1e-8f);
        g_mlpp[i0 + tid] = mlpp;
        g_cnt[i0 + tid]  = ct;
    }
}

// ---------- kernel 3: deterministic final reduction ----------
__global__ __launch_bounds__(256) void scl_finalize_kernel(
    const int* __restrict__ labels, float* __restrict__ out) {
    __shared__ float rt[256], rv[256], rb[256];
    int tid = threadIdx.x;
    float t = 0.f, nv = 0.f, nbv = 0.f;
    for (int i = tid; i < N_TOT; i += 256) {
        float ct = g_cnt[i];
        if (ct > 0.5f) {                 // valid: numerator_sums > eps
            t  += g_mlpp[i];
            nv += 1.f;
            if (labels[i] != 0) nbv += 1.f;
        }
    }
    rt[tid] = t; rv[tid] = nv; rb[tid] = nbv;
    __syncthreads();
    for (int s = 128; s > 0; s >>= 1) {
        if (tid < s) { rt[tid] += rt[tid + s]; rv[tid] += rv[tid + s]; rb[tid] += rb[tid + s]; }
        __syncthreads();
    }
    if (tid == 0) {
        float loss = -rt[0] / rv[0];
        out[0] = loss * rb[0] / (rb[0] + 1e-8f);   // bg_anchors=False rescale
    }
}

extern "C" void kernel_launch(void* const* d_in, const int* in_sizes, int n_in,
                              void* d_out, int out_size) {
    const float* stu    = (const float*)d_in[0];
    const float* tea    = (const float*)d_in[1];
    const int*   labels = (const int*)d_in[2];
    float* out = (float*)d_out;

    scl_normalize_kernel<<<N_TOT / 256, 256>>>(stu, tea);
    scl_main_kernel<<<N_TOT / RTILE, 256>>>(labels);
    scl_finalize_kernel<<<1, 256>>>(labels, out);
}

// round 2
// speedup vs baseline: 23.2340x; 23.2340x over previous
#include <cuda_runtime.h>
#include <cstdint>

// Problem constants: student/teacher [B=2, V=2, C=64, HW=1024], labels [2,2,1024]
#define N_TOT  4096   // B*V*HW
#define C_DIM  64
#define HW_DIM 1024
#define NIMG   2048   // V*HW  (only same-image pairs contribute)
#define RTILE  16     // anchor rows per block

// Scratch (device globals: no allocation allowed)
__device__ float g_sfT[C_DIM * N_TOT];   // normalized student, [C][N]
__device__ float g_tfT[C_DIM * N_TOT];   // normalized teacher, [C][N]
__device__ float g_mlpp[N_TOT];
__device__ float g_cnt[N_TOT];

// ---------- packed f32x2 helpers (Blackwell FFMA2 via PTX) ----------
__device__ __forceinline__ unsigned long long pack2(float lo, float hi) {
    unsigned long long r;
    asm("mov.b64 %0, {%1, %2};" : "=l"(r) : "f"(lo), "f"(hi));
    return r;
}
__device__ __forceinline__ void unpack2(unsigned long long v, float& lo, float& hi) {
    asm("mov.b64 {%0, %1}, %2;" : "=f"(lo), "=f"(hi) : "l"(v));
}
__device__ __forceinline__ unsigned long long ffma2(unsigned long long a,
                                                    unsigned long long b,
                                                    unsigned long long c) {
    unsigned long long d;
    asm("fma.rn.f32x2 %0, %1, %2, %3;" : "=l"(d) : "l"(a), "l"(b), "l"(c));
    return d;
}

// ---------- kernel 1: L2-normalize and transpose to [C][N] ----------
// grid (32, 2): y=0 -> student, y=1 -> teacher. 128 thr/block, 64 blocks total.
__global__ __launch_bounds__(128) void scl_normalize_kernel(
    const float* __restrict__ stu, const float* __restrict__ tea) {
    int n  = blockIdx.x * 128 + threadIdx.x;           // 0..N_TOT-1
    const float* src = blockIdx.y ? tea : stu;
    float* dst = blockIdx.y ? g_tfT : g_sfT;
    int bv = n >> 10;                                  // HW_DIM = 1024
    int p  = n & (HW_DIM - 1);

    const float* sb = src + (size_t)bv * C_DIM * HW_DIM + p;
    float v[C_DIM];
    float ss = 0.f;
#pragma unroll
    for (int c = 0; c < C_DIM; c++) { v[c] = sb[c * HW_DIM]; ss += v[c] * v[c]; }
    float inv = 1.f / fmaxf(sqrtf(ss), 1e-12f);
#pragma unroll
    for (int c = 0; c < C_DIM; c++) dst[c * N_TOT + n] = v[c] * inv;
}

// per-pair softmax bookkeeping (fixed shift M=10 since |logit| <= 1/T = 10)
__device__ __forceinline__ void scl_acc(float dot, int j, int irow_g,
                                        int labj, int labi,
                                        float& Zr, float& Sr, float& Cr) {
    float l = dot * 10.f;                // 1/TEMPERATURE
    float e = __expf(l - 10.f);
    if (j != irow_g) {                   // self-similarity excluded
        Zr += e;                         // denominator: all same-image except self
        if (labj == labi) {              // numerator: same class, except self
            Sr += l;
            Cr += 1.f;
        }
    }
}

// ---------- kernel 2: fused masked contrastive log-softmax ----------
// One block = RTILE anchor rows; each thread owns ONE column per pass,
// 8 passes cover this image's 2048 columns. Accumulator state per thread:
// 8 x u64 (f32x2 over row pairs) + Z/S/CT[16] = ~64 regs -> no spill.
__global__ __launch_bounds__(256) void scl_main_kernel(const int* __restrict__ labels) {
    __shared__ __align__(8) float sf_s[C_DIM][RTILE];   // [c][r], row-pairs LDS.64-able
    __shared__ int   lab_s[RTILE];
    __shared__ float redZ[8][RTILE], redS[8][RTILE], redC[8][RTILE];

    int tid = threadIdx.x;                    // 256 threads
    int i0  = blockIdx.x * RTILE;

    for (int idx = tid; idx < C_DIM * RTILE; idx += 256) {
        int c = idx >> 4, r = idx & (RTILE - 1);
        sf_s[c][r] = g_sfT[c * N_TOT + i0 + r];
    }
    if (tid < RTILE) lab_s[tid] = labels[i0 + tid];
    __syncthreads();

    int jbase = i0 & ~(NIMG - 1);             // this image's column block

    float Z[RTILE], S[RTILE], CT[RTILE];
#pragma unroll
    for (int r = 0; r < RTILE; r++) { Z[r] = 0.f; S[r] = 0.f; CT[r] = 0.f; }

    // 8 passes x (1 column per thread x 256 threads) = 2048 columns
    for (int g = 0; g < 8; g++) {
        int j = jbase + g * 256 + tid;

        unsigned long long acc[RTILE / 2];    // f32x2: rows (2rp, 2rp+1)
#pragma unroll
        for (int rp = 0; rp < RTILE / 2; rp++) acc[rp] = 0ull;

#pragma unroll 8
        for (int c = 0; c < C_DIM; c++) {
            float t = g_tfT[c * N_TOT + j];
            unsigned long long tp = pack2(t, t);
#pragma unroll
            for (int rp = 0; rp < RTILE / 2; rp++) {
                unsigned long long sfp =
                    *(const unsigned long long*)&sf_s[c][rp * 2];  // LDS.64 broadcast
                acc[rp] = ffma2(tp, sfp, acc[rp]);
            }
        }

        int lj = labels[j];
#pragma unroll
        for (int rp = 0; rp < RTILE / 2; rp++) {
            int r0 = rp * 2, r1 = rp * 2 + 1;
            float d0, d1;
            unpack2(acc[rp], d0, d1);
            scl_acc(d0, j, i0 + r0, lj, lab_s[r0], Z[r0], S[r0], CT[r0]);
            scl_acc(d1, j, i0 + r1, lj, lab_s[r1], Z[r1], S[r1], CT[r1]);
        }
    }

    // deterministic block reduction: warp shuffles, then cross-warp in smem
#pragma unroll
    for (int r = 0; r < RTILE; r++) {
#pragma unroll
        for (int off = 16; off > 0; off >>= 1) {
            Z[r]  += __shfl_down_sync(0xffffffffu, Z[r],  off);
            S[r]  += __shfl_down_sync(0xffffffffu, S[r],  off);
            CT[r] += __shfl_down_sync(0xffffffffu, CT[r], off);
        }
    }
    int warp = tid >> 5, lane = tid & 31;
    if (lane == 0) {
#pragma unroll
        for (int r = 0; r < RTILE; r++) {
            redZ[warp][r] = Z[r]; redS[warp][r] = S[r]; redC[warp][r] = CT[r];
        }
    }
    __syncthreads();
    if (tid < RTILE) {
        float z = 0.f, s = 0.f, ct = 0.f;
#pragma unroll
        for (int w = 0; w < 8; w++) { z += redZ[w][tid]; s += redS[w][tid]; ct += redC[w][tid]; }
        // mean log prob of positives with fixed shift M=10
        float mlpp = (s - ct * (10.f + logf(z))) / (ct + 1e-8f);
        g_mlpp[i0 + tid] = mlpp;
        g_cnt[i0 + tid]  = ct;
    }
}

// ---------- kernel 3: deterministic final reduction ----------
__global__ __launch_bounds__(256) void scl_finalize_kernel(
    const int* __restrict__ labels, float* __restrict__ out) {
    __shared__ float rt[256], rv[256], rb[256];
    int tid = threadIdx.x;
    float t = 0.f, nv = 0.f, nbv = 0.f;
    for (int i = tid; i < N_TOT; i += 256) {
        float ct = g_cnt[i];
        if (ct > 0.5f) {                 // valid: numerator_sums > eps
            t  += g_mlpp[i];
            nv += 1.f;
            if (labels[i] != 0) nbv += 1.f;
        }
    }
    rt[tid] = t; rv[tid] = nv; rb[tid] = nbv;
    __syncthreads();
    for (int s = 128; s > 0; s >>= 1) {
        if (tid < s) { rt[tid] += rt[tid + s]; rv[tid] += rv[tid + s]; rb[tid] += rb[tid + s]; }
        __syncthreads();
    }
    if (tid == 0) {
        float loss = -rt[0] / rv[0];
        out[0] = loss * rb[0] / (rb[0] + 1e-8f);   // bg_anchors=False rescale
    }
}

extern "C" void kernel_launch(void* const* d_in, const int* in_sizes, int n_in,
                              void* d_out, int out_size) {
    const float* stu    = (const float*)d_in[0];
    const float* tea    = (const float*)d_in[1];
    const int*   labels = (const int*)d_in[2];
    float* out = (float*)d_out;

    dim3 ngrid(N_TOT / 128, 2);
    scl_normalize_kernel<<<ngrid, 128>>>(stu, tea);
    scl_main_kernel<<<N_TOT / RTILE, 256>>>(labels);
    scl_finalize_kernel<<<1, 256>>>(labels, out);
}